// round 14
// baseline (speedup 1.0000x reference)
#include <cuda_runtime.h>
#include <stdint.h>

#define THREADS 512
#define NBINS   4096
#define BSHIFT  20
#define CAP     512
#define FDIM    8192
#define EPT     16            // elements per thread
#define VPT     4             // float4 vectors per thread

// Order-preserving float -> uint32 (ascending)
__device__ __forceinline__ unsigned f2key(float f) {
    unsigned u = __float_as_uint(f);
    return u ^ ((unsigned)((int)u >> 31) | 0x80000000u);
}
// Exact inverse
__device__ __forceinline__ float key2f(unsigned k) {
    unsigned m = (~(unsigned)((int)k >> 31)) | 0x80000000u;
    return __uint_as_float(k ^ m);
}

__global__ __launch_bounds__(THREADS, 4)
void topk_mask_kernel(const float* __restrict__ x, const float* __restrict__ w,
                      const int* __restrict__ kp, float* __restrict__ out)
{
    __shared__ unsigned hist[NBINS];
    __shared__ unsigned part[THREADS];
    __shared__ unsigned listKH[CAP], listIH[CAP], listKL[CAP], listIL[CAP];
    __shared__ int s_cntH, s_cntL;
    __shared__ int s_Bh, s_Bl, s_rh, s_rl;
    __shared__ unsigned s_Th, s_Ih, s_Tl, s_Il;
    __shared__ int s_red;
    __shared__ int s_K;

    const int tid  = threadIdx.x;
    const int lane = tid & 31;
    const int warp = tid >> 5;
    const int b    = blockIdx.x;

    // Per-CTA histogram rotation: decorrelates hot-bin banks across co-resident
    // CTAs. rot4 in uint4 units (0..1023); rotw in words (multiple of 4).
    const unsigned rot4 = ((unsigned)b * 2654435761u) >> 22;
    const unsigned rotw = rot4 << 2;

    if (tid == 0) { s_cntH = 0; s_cntL = 0; s_K = kp ? kp[0] : 64; }
    // clear histogram (4096 words / 512 thr = 2 uint4 each)
    ((uint4*)hist)[tid]          = make_uint4(0,0,0,0);
    ((uint4*)hist)[tid + THREADS]= make_uint4(0,0,0,0);
    __syncthreads();
    const int K = s_K;

    const float4* xr = (const float4*)(x + (size_t)b * FDIM);
    const float4* wr = (const float4*)w;
    float4* orow     = (float4*)(out + (size_t)b * FDIM);

    // ---- Phase 0: load, multiply, key, rotated histogram ----
    unsigned key[EPT];
    #pragma unroll
    for (int k = 0; k < VPT; k++) {
        int v = tid + k * THREADS;
        float4 xv = xr[v];
        float4 wv = wr[v];
        key[4*k+0] = f2key(xv.x * wv.x);
        key[4*k+1] = f2key(xv.y * wv.y);
        key[4*k+2] = f2key(xv.z * wv.z);
        key[4*k+3] = f2key(xv.w * wv.w);
        atomicAdd(&hist[((key[4*k+0] >> BSHIFT) + rotw) & (NBINS-1)], 1u);
        atomicAdd(&hist[((key[4*k+1] >> BSHIFT) + rotw) & (NBINS-1)], 1u);
        atomicAdd(&hist[((key[4*k+2] >> BSHIFT) + rotw) & (NBINS-1)], 1u);
        atomicAdd(&hist[((key[4*k+3] >> BSHIFT) + rotw) & (NBINS-1)], 1u);
    }
    __syncthreads();

    // ---- Phase 1a: partial sums of 8 logical bins each (rotated reads) ----
    {
        uint4 a = ((const uint4*)hist)[(tid*2 + rot4)     & (NBINS/4 - 1)];
        uint4 c = ((const uint4*)hist)[(tid*2 + 1 + rot4) & (NBINS/4 - 1)];
        part[tid] = a.x+a.y+a.z+a.w + c.x+c.y+c.z+c.w;
    }
    __syncthreads();

    // ---- Phase 1b: find boundary bins. warp0 = top (desc), warp1 = bottom (asc) ----
    if (warp == 0) {
        unsigned g = 0;
        #pragma unroll
        for (int p = 0; p < 16; p++) g += part[lane*16 + p];
        unsigned acc = g;
        #pragma unroll
        for (int off = 1; off < 32; off <<= 1) {
            unsigned vv = __shfl_down_sync(0xFFFFFFFFu, acc, off);
            if (lane + off < 32) acc += vv;
        }
        unsigned above = acc - g;   // strictly-above this lane's 128-bin range
        if ((int)above < K && (int)(above + g) >= K) {
            unsigned run = above;
            int base = lane * 16;
            for (int p = 15; p >= 0; --p) {
                unsigned pc = part[base + p];
                if ((int)(run + pc) >= K) {
                    int bb = (base + p) * 8;
                    for (int b8 = 7; b8 >= 0; --b8) {
                        unsigned c = hist[(unsigned)(bb + b8 + rotw) & (NBINS-1)];
                        if ((int)(run + c) >= K) { s_Bh = bb + b8; s_rh = K - (int)run; break; }
                        run += c;
                    }
                    break;
                }
                run += pc;
            }
        }
    } else if (warp == 1) {
        unsigned g = 0;
        #pragma unroll
        for (int p = 0; p < 16; p++) g += part[lane*16 + p];
        unsigned acc = g;
        #pragma unroll
        for (int off = 1; off < 32; off <<= 1) {
            unsigned vv = __shfl_up_sync(0xFFFFFFFFu, acc, off);
            if (lane >= off) acc += vv;
        }
        unsigned below = acc - g;   // strictly-below this lane's range
        if ((int)below < K && (int)(below + g) >= K) {
            unsigned run = below;
            int base = lane * 16;
            for (int p = 0; p < 16; ++p) {
                unsigned pc = part[base + p];
                if ((int)(run + pc) >= K) {
                    int bb = (base + p) * 8;
                    for (int b8 = 0; b8 < 8; ++b8) {
                        unsigned c = hist[(unsigned)(bb + b8 + rotw) & (NBINS-1)];
                        if ((int)(run + c) >= K) { s_Bl = bb + b8; s_rl = K - (int)run; break; }
                        run += c;
                    }
                    break;
                }
                run += pc;
            }
        }
    }
    __syncthreads();

    // ---- Phase 2: compact boundary-bin candidates (logical bins; unchanged) ----
    {
        const unsigned Bh = (unsigned)s_Bh, Bl = (unsigned)s_Bl;
        #pragma unroll
        for (int e = 0; e < EPT; e++) {
            unsigned bin = key[e] >> BSHIFT;
            unsigned idx = (unsigned)(tid*4 + (e>>2)*2048 + (e&3));
            if (bin == Bh) { int p = atomicAdd(&s_cntH, 1); if (p < CAP) { listKH[p] = key[e]; listIH[p] = idx; } }
            if (bin == Bl) { int p = atomicAdd(&s_cntL, 1); if (p < CAP) { listKL[p] = key[e]; listIL[p] = idx; } }
        }
    }
    __syncthreads();

    const int nH = s_cntH, nL = s_cntL;
    const bool ovH = nH > CAP, ovL = nL > CAP;

    // ---- Phase 3: exact threshold + tie index cutoff (tiny O(n^2) rank) ----
    if (!ovH && tid < nH) {
        unsigned kj = listKH[tid], ij = listIH[tid];
        int rank = 0;
        for (int i = 0; i < nH; i++) {
            unsigned ki = listKH[i], ii = listIH[i];
            rank += (ki > kj) || (ki == kj && ii < ij);
        }
        if (rank == s_rh - 1) { s_Th = kj; s_Ih = ij; }
    }
    if (!ovL && tid < nL) {
        unsigned kj = listKL[tid], ij = listIL[tid];
        int rank = 0;
        for (int i = 0; i < nL; i++) {
            unsigned ki = listKL[i], ii = listIL[i];
            rank += (ki < kj) || (ki == kj && ii < ij);
        }
        if (rank == s_rl - 1) { s_Tl = kj; s_Il = ij; }
    }

    // ---- Rare exact fallback: block-uniform binary search on keys, then on index ----
    if (ovH) {
        unsigned lo = 0, hi = 0xFFFFFFFFu;
        for (int it = 0; it < 32; ++it) {
            unsigned mid = lo + ((hi - lo) >> 1);
            if (tid == 0) s_red = 0;
            __syncthreads();
            int c = 0;
            #pragma unroll
            for (int e = 0; e < EPT; e++) c += (key[e] > mid);
            c = __reduce_add_sync(0xFFFFFFFFu, c);
            if (lane == 0) atomicAdd(&s_red, c);
            __syncthreads();
            int tot = s_red;
            __syncthreads();
            if (tot >= K) lo = mid + 1; else hi = mid;
        }
        unsigned Th = lo;
        if (tid == 0) s_red = 0;
        __syncthreads();
        { int c = 0;
          #pragma unroll
          for (int e = 0; e < EPT; e++) c += (key[e] > Th);
          c = __reduce_add_sync(0xFFFFFFFFu, c);
          if (lane == 0) atomicAdd(&s_red, c); }
        __syncthreads();
        int r = K - s_red;
        __syncthreads();
        unsigned lo2 = 0, hi2 = FDIM - 1;
        for (int it = 0; it < 13; ++it) {
            unsigned mid = lo2 + ((hi2 - lo2) >> 1);
            if (tid == 0) s_red = 0;
            __syncthreads();
            int c = 0;
            #pragma unroll
            for (int e = 0; e < EPT; e++) {
                unsigned idx = (unsigned)(tid*4 + (e>>2)*2048 + (e&3));
                c += (key[e] == Th && idx <= mid);
            }
            c = __reduce_add_sync(0xFFFFFFFFu, c);
            if (lane == 0) atomicAdd(&s_red, c);
            __syncthreads();
            int tot = s_red;
            __syncthreads();
            if (tot >= r) hi2 = mid; else lo2 = mid + 1;
        }
        if (tid == 0) { s_Th = Th; s_Ih = lo2; }
    }
    if (ovL) {
        unsigned lo = 0, hi = 0xFFFFFFFFu;
        for (int it = 0; it < 32; ++it) {
            unsigned mid = lo + ((hi - lo) >> 1);
            if (tid == 0) s_red = 0;
            __syncthreads();
            int c = 0;
            #pragma unroll
            for (int e = 0; e < EPT; e++) c += (key[e] <= mid);
            c = __reduce_add_sync(0xFFFFFFFFu, c);
            if (lane == 0) atomicAdd(&s_red, c);
            __syncthreads();
            int tot = s_red;
            __syncthreads();
            if (tot >= K) hi = mid; else lo = mid + 1;
        }
        unsigned Tl = lo;
        if (tid == 0) s_red = 0;
        __syncthreads();
        { int c = 0;
          #pragma unroll
          for (int e = 0; e < EPT; e++) c += (key[e] < Tl);
          c = __reduce_add_sync(0xFFFFFFFFu, c);
          if (lane == 0) atomicAdd(&s_red, c); }
        __syncthreads();
        int r = K - s_red;
        __syncthreads();
        unsigned lo2 = 0, hi2 = FDIM - 1;
        for (int it = 0; it < 13; ++it) {
            unsigned mid = lo2 + ((hi2 - lo2) >> 1);
            if (tid == 0) s_red = 0;
            __syncthreads();
            int c = 0;
            #pragma unroll
            for (int e = 0; e < EPT; e++) {
                unsigned idx = (unsigned)(tid*4 + (e>>2)*2048 + (e&3));
                c += (key[e] == Tl && idx <= mid);
            }
            c = __reduce_add_sync(0xFFFFFFFFu, c);
            if (lane == 0) atomicAdd(&s_red, c);
            __syncthreads();
            int tot = s_red;
            __syncthreads();
            if (tot >= r) hi2 = mid; else lo2 = mid + 1;
        }
        if (tid == 0) { s_Tl = Tl; s_Il = lo2; }
    }
    __syncthreads();

    // ---- Phase 4: masked write-out ----
    const unsigned Th = s_Th, Ih = s_Ih, Tl = s_Tl, Il = s_Il;
    #pragma unroll
    for (int k = 0; k < VPT; k++) {
        float vals[4];
        #pragma unroll
        for (int c = 0; c < 4; c++) {
            unsigned kk  = key[4*k + c];
            unsigned idx = (unsigned)(tid*4 + k*2048 + c);
            bool z = (kk > Th) || (kk < Tl) ||
                     (kk == Th && idx <= Ih) ||
                     (kk == Tl && idx <= Il);
            vals[c] = z ? 0.0f : key2f(kk);
        }
        float4 o; o.x = vals[0]; o.y = vals[1]; o.z = vals[2]; o.w = vals[3];
        orow[tid + k * THREADS] = o;
    }
}

extern "C" void kernel_launch(void* const* d_in, const int* in_sizes, int n_in,
                              void* d_out, int out_size)
{
    const float* x = (const float*)d_in[0];
    const float* w = (const float*)d_in[1];
    const int* kp  = (n_in >= 3) ? (const int*)d_in[2] : nullptr;

    int Fdim = in_sizes[1];
    int B    = in_sizes[0] / Fdim;

    topk_mask_kernel<<<B, THREADS>>>(x, w, kp, (float*)d_out);
}

// round 15
// speedup vs baseline: 1.0837x; 1.0837x over previous
#include <cuda_runtime.h>
#include <stdint.h>

#define THREADS 512
#define NBINS   2048
#define BSHIFT  21            // key >> 21 -> 2048 bins
#define CAP     512
#define FDIM    8192
#define EPT     16            // elements per thread
#define VPT     4             // float4 vectors per thread

// Order-preserving float -> uint32 (ascending)
__device__ __forceinline__ unsigned f2key(float f) {
    unsigned u = __float_as_uint(f);
    return u ^ ((unsigned)((int)u >> 31) | 0x80000000u);
}
// Exact inverse
__device__ __forceinline__ float key2f(unsigned k) {
    unsigned m = (~(unsigned)((int)k >> 31)) | 0x80000000u;
    return __uint_as_float(k ^ m);
}

__global__ __launch_bounds__(THREADS, 3)
void topk_mask_kernel(const float* __restrict__ x, const float* __restrict__ w,
                      const int* __restrict__ kp, float* __restrict__ out)
{
    __shared__ unsigned hist[NBINS];
    __shared__ unsigned part[THREADS];
    __shared__ unsigned listKH[CAP], listIH[CAP], listKL[CAP], listIL[CAP];
    __shared__ int s_cntH, s_cntL;
    __shared__ int s_Bh, s_Bl, s_rh, s_rl;
    __shared__ unsigned s_Th, s_Ih, s_Tl, s_Il;
    __shared__ int s_red;
    __shared__ int s_K;

    const int tid  = threadIdx.x;
    const int lane = tid & 31;
    const int warp = tid >> 5;
    const int b    = blockIdx.x;

    if (tid == 0) { s_cntH = 0; s_cntL = 0; s_K = kp ? kp[0] : 64; }
    // clear histogram (2048 words = 512 * uint4)
    ((uint4*)hist)[tid] = make_uint4(0,0,0,0);
    __syncthreads();
    const int K = s_K;

    const float4* xr = (const float4*)(x + (size_t)b * FDIM);
    const float4* wr = (const float4*)w;
    float4* orow     = (float4*)(out + (size_t)b * FDIM);

    // ---- Phase 0: load, multiply, key, histogram ----
    unsigned key[EPT];
    #pragma unroll
    for (int k = 0; k < VPT; k++) {
        int v = tid + k * THREADS;
        float4 xv = xr[v];
        float4 wv = wr[v];
        key[4*k+0] = f2key(xv.x * wv.x);
        key[4*k+1] = f2key(xv.y * wv.y);
        key[4*k+2] = f2key(xv.z * wv.z);
        key[4*k+3] = f2key(xv.w * wv.w);
        atomicAdd(&hist[key[4*k+0] >> BSHIFT], 1u);
        atomicAdd(&hist[key[4*k+1] >> BSHIFT], 1u);
        atomicAdd(&hist[key[4*k+2] >> BSHIFT], 1u);
        atomicAdd(&hist[key[4*k+3] >> BSHIFT], 1u);
    }
    __syncthreads();

    // ---- Phase 1a: partial sums of 4 bins each ----
    {
        uint4 a = ((const uint4*)hist)[tid];
        part[tid] = a.x + a.y + a.z + a.w;
    }
    __syncthreads();

    // ---- Phase 1b: find boundary bins. warp0 = top (desc), warp1 = bottom (asc) ----
    if (warp == 0) {
        unsigned g = 0;
        #pragma unroll
        for (int p = 0; p < 16; p++) g += part[lane*16 + p];
        unsigned acc = g;
        #pragma unroll
        for (int off = 1; off < 32; off <<= 1) {
            unsigned vv = __shfl_down_sync(0xFFFFFFFFu, acc, off);
            if (lane + off < 32) acc += vv;
        }
        unsigned above = acc - g;   // strictly-above this lane's 64-bin range
        if ((int)above < K && (int)(above + g) >= K) {
            unsigned run = above;
            int base = lane * 16;
            for (int p = 15; p >= 0; --p) {
                unsigned pc = part[base + p];
                if ((int)(run + pc) >= K) {
                    int bb = (base + p) * 4;
                    for (int b4 = 3; b4 >= 0; --b4) {
                        unsigned c = hist[bb + b4];
                        if ((int)(run + c) >= K) { s_Bh = bb + b4; s_rh = K - (int)run; break; }
                        run += c;
                    }
                    break;
                }
                run += pc;
            }
        }
    } else if (warp == 1) {
        unsigned g = 0;
        #pragma unroll
        for (int p = 0; p < 16; p++) g += part[lane*16 + p];
        unsigned acc = g;
        #pragma unroll
        for (int off = 1; off < 32; off <<= 1) {
            unsigned vv = __shfl_up_sync(0xFFFFFFFFu, acc, off);
            if (lane >= off) acc += vv;
        }
        unsigned below = acc - g;   // strictly-below this lane's range
        if ((int)below < K && (int)(below + g) >= K) {
            unsigned run = below;
            int base = lane * 16;
            for (int p = 0; p < 16; ++p) {
                unsigned pc = part[base + p];
                if ((int)(run + pc) >= K) {
                    int bb = (base + p) * 4;
                    for (int b4 = 0; b4 < 4; ++b4) {
                        unsigned c = hist[bb + b4];
                        if ((int)(run + c) >= K) { s_Bl = bb + b4; s_rl = K - (int)run; break; }
                        run += c;
                    }
                    break;
                }
                run += pc;
            }
        }
    }
    __syncthreads();

    // ---- Phase 2: compact boundary-bin candidates (key, idx) ----
    {
        const unsigned Bh = (unsigned)s_Bh, Bl = (unsigned)s_Bl;
        #pragma unroll
        for (int e = 0; e < EPT; e++) {
            unsigned bin = key[e] >> BSHIFT;
            unsigned idx = (unsigned)(tid*4 + (e>>2)*2048 + (e&3));
            if (bin == Bh) { int p = atomicAdd(&s_cntH, 1); if (p < CAP) { listKH[p] = key[e]; listIH[p] = idx; } }
            if (bin == Bl) { int p = atomicAdd(&s_cntL, 1); if (p < CAP) { listKL[p] = key[e]; listIL[p] = idx; } }
        }
    }
    __syncthreads();

    const int nH = s_cntH, nL = s_cntL;
    const bool ovH = nH > CAP, ovL = nL > CAP;

    // ---- Phase 3: exact threshold + tie index cutoff (tiny O(n^2) rank) ----
    if (!ovH && tid < nH) {
        unsigned kj = listKH[tid], ij = listIH[tid];
        int rank = 0;
        for (int i = 0; i < nH; i++) {
            unsigned ki = listKH[i], ii = listIH[i];
            rank += (ki > kj) || (ki == kj && ii < ij);
        }
        if (rank == s_rh - 1) { s_Th = kj; s_Ih = ij; }
    }
    if (!ovL && tid < nL) {
        unsigned kj = listKL[tid], ij = listIL[tid];
        int rank = 0;
        for (int i = 0; i < nL; i++) {
            unsigned ki = listKL[i], ii = listIL[i];
            rank += (ki < kj) || (ki == kj && ii < ij);
        }
        if (rank == s_rl - 1) { s_Tl = kj; s_Il = ij; }
    }

    // ---- Rare exact fallback: block-uniform binary search on keys, then on index ----
    if (ovH) {
        unsigned lo = 0, hi = 0xFFFFFFFFu;
        for (int it = 0; it < 32; ++it) {
            unsigned mid = lo + ((hi - lo) >> 1);
            if (tid == 0) s_red = 0;
            __syncthreads();
            int c = 0;
            #pragma unroll
            for (int e = 0; e < EPT; e++) c += (key[e] > mid);
            c = __reduce_add_sync(0xFFFFFFFFu, c);
            if (lane == 0) atomicAdd(&s_red, c);
            __syncthreads();
            int tot = s_red;
            __syncthreads();
            if (tot >= K) lo = mid + 1; else hi = mid;
        }
        unsigned Th = lo;
        if (tid == 0) s_red = 0;
        __syncthreads();
        { int c = 0;
          #pragma unroll
          for (int e = 0; e < EPT; e++) c += (key[e] > Th);
          c = __reduce_add_sync(0xFFFFFFFFu, c);
          if (lane == 0) atomicAdd(&s_red, c); }
        __syncthreads();
        int r = K - s_red;
        __syncthreads();
        unsigned lo2 = 0, hi2 = FDIM - 1;
        for (int it = 0; it < 13; ++it) {
            unsigned mid = lo2 + ((hi2 - lo2) >> 1);
            if (tid == 0) s_red = 0;
            __syncthreads();
            int c = 0;
            #pragma unroll
            for (int e = 0; e < EPT; e++) {
                unsigned idx = (unsigned)(tid*4 + (e>>2)*2048 + (e&3));
                c += (key[e] == Th && idx <= mid);
            }
            c = __reduce_add_sync(0xFFFFFFFFu, c);
            if (lane == 0) atomicAdd(&s_red, c);
            __syncthreads();
            int tot = s_red;
            __syncthreads();
            if (tot >= r) hi2 = mid; else lo2 = mid + 1;
        }
        if (tid == 0) { s_Th = Th; s_Ih = lo2; }
    }
    if (ovL) {
        unsigned lo = 0, hi = 0xFFFFFFFFu;
        for (int it = 0; it < 32; ++it) {
            unsigned mid = lo + ((hi - lo) >> 1);
            if (tid == 0) s_red = 0;
            __syncthreads();
            int c = 0;
            #pragma unroll
            for (int e = 0; e < EPT; e++) c += (key[e] <= mid);
            c = __reduce_add_sync(0xFFFFFFFFu, c);
            if (lane == 0) atomicAdd(&s_red, c);
            __syncthreads();
            int tot = s_red;
            __syncthreads();
            if (tot >= K) hi = mid; else lo = mid + 1;
        }
        unsigned Tl = lo;
        if (tid == 0) s_red = 0;
        __syncthreads();
        { int c = 0;
          #pragma unroll
          for (int e = 0; e < EPT; e++) c += (key[e] < Tl);
          c = __reduce_add_sync(0xFFFFFFFFu, c);
          if (lane == 0) atomicAdd(&s_red, c); }
        __syncthreads();
        int r = K - s_red;
        __syncthreads();
        unsigned lo2 = 0, hi2 = FDIM - 1;
        for (int it = 0; it < 13; ++it) {
            unsigned mid = lo2 + ((hi2 - lo2) >> 1);
            if (tid == 0) s_red = 0;
            __syncthreads();
            int c = 0;
            #pragma unroll
            for (int e = 0; e < EPT; e++) {
                unsigned idx = (unsigned)(tid*4 + (e>>2)*2048 + (e&3));
                c += (key[e] == Tl && idx <= mid);
            }
            c = __reduce_add_sync(0xFFFFFFFFu, c);
            if (lane == 0) atomicAdd(&s_red, c);
            __syncthreads();
            int tot = s_red;
            __syncthreads();
            if (tot >= r) hi2 = mid; else lo2 = mid + 1;
        }
        if (tid == 0) { s_Tl = Tl; s_Il = lo2; }
    }
    __syncthreads();

    // ---- Phase 4: masked write-out ----
    const unsigned Th = s_Th, Ih = s_Ih, Tl = s_Tl, Il = s_Il;
    #pragma unroll
    for (int k = 0; k < VPT; k++) {
        float vals[4];
        #pragma unroll
        for (int c = 0; c < 4; c++) {
            unsigned kk  = key[4*k + c];
            unsigned idx = (unsigned)(tid*4 + k*2048 + c);
            bool z = (kk > Th) || (kk < Tl) ||
                     (kk == Th && idx <= Ih) ||
                     (kk == Tl && idx <= Il);
            vals[c] = z ? 0.0f : key2f(kk);
        }
        float4 o; o.x = vals[0]; o.y = vals[1]; o.z = vals[2]; o.w = vals[3];
        orow[tid + k * THREADS] = o;
    }
}

extern "C" void kernel_launch(void* const* d_in, const int* in_sizes, int n_in,
                              void* d_out, int out_size)
{
    const float* x = (const float*)d_in[0];
    const float* w = (const float*)d_in[1];
    const int* kp  = (n_in >= 3) ? (const int*)d_in[2] : nullptr;

    int Fdim = in_sizes[1];
    int B    = in_sizes[0] / Fdim;

    topk_mask_kernel<<<B, THREADS>>>(x, w, kp, (float*)d_out);
}

// round 17
// speedup vs baseline: 1.6489x; 1.5215x over previous
#include <cuda_runtime.h>
#include <stdint.h>

#define THREADS 512
#define NBINS   8192
#define BSHIFT  19            // key >> 19 -> 8192 bins
#define CAP     512
#define FDIM    8192
#define EPT     16            // elements per thread
#define VPT     4             // float4 vectors per thread

// Order-preserving float -> uint32 (ascending)
__device__ __forceinline__ unsigned f2key(float f) {
    unsigned u = __float_as_uint(f);
    return u ^ ((unsigned)((int)u >> 31) | 0x80000000u);
}
// Exact inverse
__device__ __forceinline__ float key2f(unsigned k) {
    unsigned m = (~(unsigned)((int)k >> 31)) | 0x80000000u;
    return __uint_as_float(k ^ m);
}

__global__ __launch_bounds__(THREADS, 3)
void topk_mask_kernel(const float* __restrict__ x, const float* __restrict__ w,
                      const int* __restrict__ kp, float* __restrict__ out)
{
    __shared__ unsigned hist[NBINS];                 // 32 KB
    __shared__ unsigned part[THREADS];               // 2 KB
    __shared__ unsigned listKH[CAP], listIH[CAP], listKL[CAP], listIL[CAP];
    __shared__ int s_cntH, s_cntL;
    __shared__ int s_Bh, s_Bl, s_rh, s_rl;
    __shared__ unsigned s_Th, s_Ih, s_Tl, s_Il;
    __shared__ int s_red;
    __shared__ int s_K;

    const int tid  = threadIdx.x;
    const int lane = tid & 31;
    const int warp = tid >> 5;
    const int b    = blockIdx.x;

    if (tid == 0) { s_cntH = 0; s_cntL = 0; s_K = kp ? kp[0] : 64; }
    // clear histogram (8192 words / 512 thr = 4 uint4 each)
    ((uint4*)hist)[tid]              = make_uint4(0,0,0,0);
    ((uint4*)hist)[tid + THREADS]    = make_uint4(0,0,0,0);
    ((uint4*)hist)[tid + 2*THREADS]  = make_uint4(0,0,0,0);
    ((uint4*)hist)[tid + 3*THREADS]  = make_uint4(0,0,0,0);
    __syncthreads();
    const int K = s_K;

    const float4* xr = (const float4*)(x + (size_t)b * FDIM);
    const float4* wr = (const float4*)w;
    float4* orow     = (float4*)(out + (size_t)b * FDIM);

    // ---- Phase 0: load, multiply, key, histogram ----
    unsigned key[EPT];
    #pragma unroll
    for (int k = 0; k < VPT; k++) {
        int v = tid + k * THREADS;
        float4 xv = xr[v];
        float4 wv = wr[v];
        key[4*k+0] = f2key(xv.x * wv.x);
        key[4*k+1] = f2key(xv.y * wv.y);
        key[4*k+2] = f2key(xv.z * wv.z);
        key[4*k+3] = f2key(xv.w * wv.w);
        atomicAdd(&hist[key[4*k+0] >> BSHIFT], 1u);
        atomicAdd(&hist[key[4*k+1] >> BSHIFT], 1u);
        atomicAdd(&hist[key[4*k+2] >> BSHIFT], 1u);
        atomicAdd(&hist[key[4*k+3] >> BSHIFT], 1u);
    }
    __syncthreads();

    // ---- Phase 1a: partial sums of 16 bins each ----
    {
        uint4 a0 = ((const uint4*)hist)[tid*4];
        uint4 a1 = ((const uint4*)hist)[tid*4+1];
        uint4 a2 = ((const uint4*)hist)[tid*4+2];
        uint4 a3 = ((const uint4*)hist)[tid*4+3];
        part[tid] = a0.x+a0.y+a0.z+a0.w + a1.x+a1.y+a1.z+a1.w
                  + a2.x+a2.y+a2.z+a2.w + a3.x+a3.y+a3.z+a3.w;
    }
    __syncthreads();

    // ---- Phase 1b: find boundary bins. warp0 = top (desc), warp1 = bottom (asc) ----
    if (warp == 0) {
        unsigned g = 0;
        #pragma unroll
        for (int p = 0; p < 16; p++) g += part[lane*16 + p];
        unsigned acc = g;
        #pragma unroll
        for (int off = 1; off < 32; off <<= 1) {
            unsigned vv = __shfl_down_sync(0xFFFFFFFFu, acc, off);
            if (lane + off < 32) acc += vv;
        }
        unsigned above = acc - g;   // strictly-above this lane's 256-bin range
        if ((int)above < K && (int)(above + g) >= K) {
            unsigned run = above;
            int base = lane * 16;
            for (int p = 15; p >= 0; --p) {
                unsigned pc = part[base + p];
                if ((int)(run + pc) >= K) {
                    int bb = (base + p) * 16;
                    for (int b16 = 15; b16 >= 0; --b16) {
                        unsigned c = hist[bb + b16];
                        if ((int)(run + c) >= K) { s_Bh = bb + b16; s_rh = K - (int)run; break; }
                        run += c;
                    }
                    break;
                }
                run += pc;
            }
        }
    } else if (warp == 1) {
        unsigned g = 0;
        #pragma unroll
        for (int p = 0; p < 16; p++) g += part[lane*16 + p];
        unsigned acc = g;
        #pragma unroll
        for (int off = 1; off < 32; off <<= 1) {
            unsigned vv = __shfl_up_sync(0xFFFFFFFFu, acc, off);
            if (lane >= off) acc += vv;
        }
        unsigned below = acc - g;   // strictly-below this lane's range
        if ((int)below < K && (int)(below + g) >= K) {
            unsigned run = below;
            int base = lane * 16;
            for (int p = 0; p < 16; ++p) {
                unsigned pc = part[base + p];
                if ((int)(run + pc) >= K) {
                    int bb = (base + p) * 16;
                    for (int b16 = 0; b16 < 16; ++b16) {
                        unsigned c = hist[bb + b16];
                        if ((int)(run + c) >= K) { s_Bl = bb + b16; s_rl = K - (int)run; break; }
                        run += c;
                    }
                    break;
                }
                run += pc;
            }
        }
    }
    __syncthreads();

    // ---- Phase 2: compact boundary-bin candidates (key, idx) ----
    {
        const unsigned Bh = (unsigned)s_Bh, Bl = (unsigned)s_Bl;
        #pragma unroll
        for (int e = 0; e < EPT; e++) {
            unsigned bin = key[e] >> BSHIFT;
            unsigned idx = (unsigned)(tid*4 + (e>>2)*2048 + (e&3));
            if (bin == Bh) { int p = atomicAdd(&s_cntH, 1); if (p < CAP) { listKH[p] = key[e]; listIH[p] = idx; } }
            if (bin == Bl) { int p = atomicAdd(&s_cntL, 1); if (p < CAP) { listKL[p] = key[e]; listIL[p] = idx; } }
        }
    }
    __syncthreads();

    const int nH = s_cntH, nL = s_cntL;
    const bool ovH = nH > CAP, ovL = nL > CAP;

    // ---- Phase 3: exact threshold + tie index cutoff (tiny O(n^2) rank) ----
    if (!ovH && tid < nH) {
        unsigned kj = listKH[tid], ij = listIH[tid];
        int rank = 0;
        for (int i = 0; i < nH; i++) {
            unsigned ki = listKH[i], ii = listIH[i];
            rank += (ki > kj) || (ki == kj && ii < ij);
        }
        if (rank == s_rh - 1) { s_Th = kj; s_Ih = ij; }
    }
    if (!ovL && tid < nL) {
        unsigned kj = listKL[tid], ij = listIL[tid];
        int rank = 0;
        for (int i = 0; i < nL; i++) {
            unsigned ki = listKL[i], ii = listIL[i];
            rank += (ki < kj) || (ki == kj && ii < ij);
        }
        if (rank == s_rl - 1) { s_Tl = kj; s_Il = ij; }
    }

    // ---- Rare exact fallback: block-uniform binary search on keys, then on index ----
    if (ovH) {
        unsigned lo = 0, hi = 0xFFFFFFFFu;
        for (int it = 0; it < 32; ++it) {
            unsigned mid = lo + ((hi - lo) >> 1);
            if (tid == 0) s_red = 0;
            __syncthreads();
            int c = 0;
            #pragma unroll
            for (int e = 0; e < EPT; e++) c += (key[e] > mid);
            c = __reduce_add_sync(0xFFFFFFFFu, c);
            if (lane == 0) atomicAdd(&s_red, c);
            __syncthreads();
            int tot = s_red;
            __syncthreads();
            if (tot >= K) lo = mid + 1; else hi = mid;
        }
        unsigned Th = lo;
        if (tid == 0) s_red = 0;
        __syncthreads();
        { int c = 0;
          #pragma unroll
          for (int e = 0; e < EPT; e++) c += (key[e] > Th);
          c = __reduce_add_sync(0xFFFFFFFFu, c);
          if (lane == 0) atomicAdd(&s_red, c); }
        __syncthreads();
        int r = K - s_red;
        __syncthreads();
        unsigned lo2 = 0, hi2 = FDIM - 1;
        for (int it = 0; it < 13; ++it) {
            unsigned mid = lo2 + ((hi2 - lo2) >> 1);
            if (tid == 0) s_red = 0;
            __syncthreads();
            int c = 0;
            #pragma unroll
            for (int e = 0; e < EPT; e++) {
                unsigned idx = (unsigned)(tid*4 + (e>>2)*2048 + (e&3));
                c += (key[e] == Th && idx <= mid);
            }
            c = __reduce_add_sync(0xFFFFFFFFu, c);
            if (lane == 0) atomicAdd(&s_red, c);
            __syncthreads();
            int tot = s_red;
            __syncthreads();
            if (tot >= r) hi2 = mid; else lo2 = mid + 1;
        }
        if (tid == 0) { s_Th = Th; s_Ih = lo2; }
    }
    if (ovL) {
        unsigned lo = 0, hi = 0xFFFFFFFFu;
        for (int it = 0; it < 32; ++it) {
            unsigned mid = lo + ((hi - lo) >> 1);
            if (tid == 0) s_red = 0;
            __syncthreads();
            int c = 0;
            #pragma unroll
            for (int e = 0; e < EPT; e++) c += (key[e] <= mid);
            c = __reduce_add_sync(0xFFFFFFFFu, c);
            if (lane == 0) atomicAdd(&s_red, c);
            __syncthreads();
            int tot = s_red;
            __syncthreads();
            if (tot >= K) hi = mid; else lo = mid + 1;
        }
        unsigned Tl = lo;
        if (tid == 0) s_red = 0;
        __syncthreads();
        { int c = 0;
          #pragma unroll
          for (int e = 0; e < EPT; e++) c += (key[e] < Tl);
          c = __reduce_add_sync(0xFFFFFFFFu, c);
          if (lane == 0) atomicAdd(&s_red, c); }
        __syncthreads();
        int r = K - s_red;
        __syncthreads();
        unsigned lo2 = 0, hi2 = FDIM - 1;
        for (int it = 0; it < 13; ++it) {
            unsigned mid = lo2 + ((hi2 - lo2) >> 1);
            if (tid == 0) s_red = 0;
            __syncthreads();
            int c = 0;
            #pragma unroll
            for (int e = 0; e < EPT; e++) {
                unsigned idx = (unsigned)(tid*4 + (e>>2)*2048 + (e&3));
                c += (key[e] == Tl && idx <= mid);
            }
            c = __reduce_add_sync(0xFFFFFFFFu, c);
            if (lane == 0) atomicAdd(&s_red, c);
            __syncthreads();
            int tot = s_red;
            __syncthreads();
            if (tot >= r) hi2 = mid; else lo2 = mid + 1;
        }
        if (tid == 0) { s_Tl = Tl; s_Il = lo2; }
    }
    __syncthreads();

    // ---- Phase 4: masked write-out ----
    const unsigned Th = s_Th, Ih = s_Ih, Tl = s_Tl, Il = s_Il;
    #pragma unroll
    for (int k = 0; k < VPT; k++) {
        float vals[4];
        #pragma unroll
        for (int c = 0; c < 4; c++) {
            unsigned kk  = key[4*k + c];
            unsigned idx = (unsigned)(tid*4 + k*2048 + c);
            bool z = (kk > Th) || (kk < Tl) ||
                     (kk == Th && idx <= Ih) ||
                     (kk == Tl && idx <= Il);
            vals[c] = z ? 0.0f : key2f(kk);
        }
        float4 o; o.x = vals[0]; o.y = vals[1]; o.z = vals[2]; o.w = vals[3];
        orow[tid + k * THREADS] = o;
    }
}

extern "C" void kernel_launch(void* const* d_in, const int* in_sizes, int n_in,
                              void* d_out, int out_size)
{
    const float* x = (const float*)d_in[0];
    const float* w = (const float*)d_in[1];
    const int* kp  = (n_in >= 3) ? (const int*)d_in[2] : nullptr;

    int Fdim = in_sizes[1];
    int B    = in_sizes[0] / Fdim;

    topk_mask_kernel<<<B, THREADS>>>(x, w, kp, (float*)d_out);
}